// round 1
// baseline (speedup 1.0000x reference)
#include <cuda_runtime.h>
#include <cuda_bf16.h>
#include <math.h>

// Problem constants
#define NGRAPH 1024
#define S 64
#define NNODE (NGRAPH * S)          // 65536
#define EPG 1024                    // edges per graph = S*DEG
#define E_TOTAL (NGRAPH * EPG)      // 1048576
#define FEAT 64
#define HID 256
#define NCLS 16
#define BN_COUNT 65536.0f
#define EPS 1e-5f

// Scratch (device globals; no allocation allowed)
__device__ float g_buf1[NGRAPH * S * FEAT];   // 16 MB
__device__ float g_buf2[NGRAPH * S * FEAT];   // 16 MB
__device__ float g_act1[NGRAPH * HID];
__device__ float g_act2[NGRAPH * HID];
__device__ float g_stats[384];                // 3 BNs x (64 sum + 64 sumsq)

// ---------------------------------------------------------------------------
__global__ void zero_stats_kernel(float* st) {
    int i = threadIdx.x;
    if (i < 384) st[i] = 0.f;
}

// ---------------------------------------------------------------------------
// EdgeConv: one block per graph. Counting-sort edges by dst into shared,
// then per-(node,feature) serial accumulation (no scatter atomics).
// out layout: [(g*64 + node)*64 + feat]  (node-major rows, feature cols)
__global__ void edgeconv_kernel(const float* __restrict__ x,
                                const int* __restrict__ ei,
                                const float* __restrict__ w1,
                                const float* __restrict__ b1,
                                const float* __restrict__ w2,
                                const float* __restrict__ b2,
                                float* __restrict__ out) {
    __shared__ float sx[64];
    __shared__ float sw2[4][64];
    __shared__ float sb2v[64];
    __shared__ float sw1v[8];
    __shared__ float sb1v[4];
    __shared__ int s_src[EPG];
    __shared__ int s_d[EPG];
    __shared__ float shh[EPG * 4];     // per-edge hidden (4), sorted by dst
    __shared__ int cnt[64], off[64], pos[64];

    int g = blockIdx.x, tid = threadIdx.x;
    const int* srcp = ei + g * EPG;
    const int* dstp = ei + E_TOTAL + g * EPG;

    if (tid < 64) {
        sx[tid] = x[g * 64 + tid];
        sb2v[tid] = b2[tid];
        sw2[0][tid] = w2[tid];
        sw2[1][tid] = w2[64 + tid];
        sw2[2][tid] = w2[128 + tid];
        sw2[3][tid] = w2[192 + tid];
        cnt[tid] = 0;
    }
    if (tid < 8) sw1v[tid] = w1[tid];
    if (tid < 4) sb1v[tid] = b1[tid];
    __syncthreads();

    // histogram by dst
    for (int e = tid; e < EPG; e += 256) {
        int s = srcp[e] & 63;
        int d = dstp[e] & 63;
        s_src[e] = s;
        s_d[e] = d;
        atomicAdd(&cnt[d], 1);
    }
    __syncthreads();
    if (tid == 0) {
        int a = 0;
        for (int i = 0; i < 64; i++) { off[i] = a; a += cnt[i]; }
    }
    __syncthreads();
    if (tid < 64) pos[tid] = off[tid];
    __syncthreads();

    // compute per-edge hidden h[4] and place at sorted position
    float wa0 = sw1v[0], wa1 = sw1v[1], wa2 = sw1v[2], wa3 = sw1v[3];
    float wb0 = sw1v[4], wb1 = sw1v[5], wb2 = sw1v[6], wb3 = sw1v[7];
    float c0 = sb1v[0], c1 = sb1v[1], c2 = sb1v[2], c3 = sb1v[3];
    for (int e = tid; e < EPG; e += 256) {
        int d = s_d[e];
        float xi = sx[d];
        float xd = sx[s_src[e]] - xi;
        float h0 = fmaxf(fmaf(xd, wb0, fmaf(xi, wa0, c0)), 0.f);
        float h1 = fmaxf(fmaf(xd, wb1, fmaf(xi, wa1, c1)), 0.f);
        float h2 = fmaxf(fmaf(xd, wb2, fmaf(xi, wa2, c2)), 0.f);
        float h3 = fmaxf(fmaf(xd, wb3, fmaf(xi, wa3, c3)), 0.f);
        int p = atomicAdd(&pos[d], 1);
        float4 hv = make_float4(h0, h1, h2, h3);
        *(float4*)&shh[p * 4] = hv;
    }
    __syncthreads();

    // accumulate per (node d, feature f); warp-uniform d => no divergence
    int f = tid & 63, dq = tid >> 6;
    float u0 = sw2[0][f], u1 = sw2[1][f], u2 = sw2[2][f], u3 = sw2[3][f];
    float bb = sb2v[f];
    float* out_g = out + g * 4096;
    for (int d = dq; d < 64; d += 4) {
        int st = off[d], en = st + cnt[d];
        float acc = bb * (float)(en - st);      // b2 added once per edge
        for (int e = st; e < en; e++) {
            float4 h = *(const float4*)&shh[e * 4];
            acc = fmaf(h.x, u0, acc);
            acc = fmaf(h.y, u1, acc);
            acc = fmaf(h.z, u2, acc);
            acc = fmaf(h.w, u3, acc);
        }
        out_g[d * 64 + f] = acc;
    }
}

// ---------------------------------------------------------------------------
// BN stats, channel = column (&63). buf: [65536 rows][64 cols]. grid 1024.
__global__ void stats_colch_kernel(const float* __restrict__ buf, float* __restrict__ st) {
    __shared__ float ps[4][64], pq[4][64];
    int b = blockIdx.x, tid = threadIdx.x;
    int f = tid & 63, rq = tid >> 6;
    const float* base = buf + b * 4096;
    float s = 0.f, q = 0.f;
    for (int r = rq; r < 64; r += 4) {
        float v = base[r * 64 + f];
        s += v;
        q += v * v;
    }
    ps[rq][f] = s;
    pq[rq][f] = q;
    __syncthreads();
    if (tid < 64) {
        float SS = ps[0][tid] + ps[1][tid] + ps[2][tid] + ps[3][tid];
        float QQ = pq[0][tid] + pq[1][tid] + pq[2][tid] + pq[3][tid];
        atomicAdd(&st[tid], SS);
        atomicAdd(&st[64 + tid], QQ);
    }
}

// BN stats, channel = row (&63), sum over 64 cols. block per graph. grid 1024.
__global__ void stats_rowch_kernel(const float* __restrict__ buf, float* __restrict__ st) {
    int b = blockIdx.x, tid = threadIdx.x;
    int o = tid >> 2, q = tid & 3;
    const float* row = buf + b * 4096 + o * 64 + q * 16;
    float s = 0.f, sq = 0.f;
#pragma unroll
    for (int i = 0; i < 4; i++) {
        float4 v = *(const float4*)&row[i * 4];
        s += v.x + v.y + v.z + v.w;
        sq += v.x * v.x + v.y * v.y + v.z * v.z + v.w * v.w;
    }
    s += __shfl_xor_sync(0xffffffffu, s, 1);
    sq += __shfl_xor_sync(0xffffffffu, sq, 1);
    s += __shfl_xor_sync(0xffffffffu, s, 2);
    sq += __shfl_xor_sync(0xffffffffu, sq, 2);
    if (q == 0) {
        atomicAdd(&st[o], s);
        atomicAdd(&st[64 + o], sq);
    }
}

// ---------------------------------------------------------------------------
// Fused BN(+ReLU on input) + Conv1d(64,64,k=3,pad=1). One block per graph.
// TIN=true:  input node-major  in[(g*64+l)*64+i]  (channel i = column)
// TIN=false: input chan-major  in[(g*64+i)*64+l]  (channel i = row)
// Output: [(g*64+o)*64+l] (pre-BN conv result).
#define CONV_SMEM ((64 * 66 + 3 * 4096 + 128) * 4)
template <bool TIN>
__global__ void conv_bn_kernel(const float* __restrict__ in,
                               const float* __restrict__ st,
                               const float* __restrict__ gamma,
                               const float* __restrict__ beta,
                               const float* __restrict__ cw,
                               const float* __restrict__ cb,
                               float* __restrict__ out) {
    extern __shared__ float smem[];
    float* sh = smem;                 // [64][66], position p at index p+1
    float* sw0 = smem + 64 * 66;      // [o*64 + i]
    float* sw1 = sw0 + 4096;
    float* sw2p = sw1 + 4096;
    float* sscale = sw2p + 4096;      // [64]
    float* sshift = sscale + 64;      // [64]

    int g = blockIdx.x, tid = threadIdx.x;

    for (int idx = tid; idx < 4096; idx += 256) {
        sw0[idx] = cw[idx * 3];
        sw1[idx] = cw[idx * 3 + 1];
        sw2p[idx] = cw[idx * 3 + 2];
    }
    if (tid < 64) {
        float mean = st[tid] * (1.f / BN_COUNT);
        float var = st[64 + tid] * (1.f / BN_COUNT) - mean * mean;
        float inv = rsqrtf(var + EPS);
        float sc = gamma[tid] * inv;
        sscale[tid] = sc;
        sshift[tid] = beta[tid] - mean * sc;
        sh[tid * 66] = 0.f;
        sh[tid * 66 + 65] = 0.f;
    }
    __syncthreads();

    const float* in_g = in + g * 4096;
    for (int idx = tid; idx < 4096; idx += 256) {
        int i, l;
        if (TIN) { l = idx >> 6; i = idx & 63; }
        else     { i = idx >> 6; l = idx & 63; }
        float v = in_g[idx];
        sh[i * 66 + l + 1] = fmaxf(fmaf(v, sscale[i], sshift[i]), 0.f);
    }
    __syncthreads();

    int l = tid & 63, ob = tid >> 6;
    float acc[16];
#pragma unroll
    for (int j = 0; j < 16; j++) acc[j] = cb[ob * 16 + j];

    for (int ic = 0; ic < 16; ic++) {
        float A0[4], A1[4], A2[4];
#pragma unroll
        for (int ii = 0; ii < 4; ii++) {
            const float* r = &sh[(ic * 4 + ii) * 66 + l];
            A0[ii] = r[0];
            A1[ii] = r[1];
            A2[ii] = r[2];
        }
#pragma unroll
        for (int j = 0; j < 16; j++) {
            int o = ob * 16 + j;
            float4 w0 = *(const float4*)&sw0[o * 64 + ic * 4];
            float4 w1 = *(const float4*)&sw1[o * 64 + ic * 4];
            float4 w2 = *(const float4*)&sw2p[o * 64 + ic * 4];
            float a = acc[j];
            a = fmaf(A0[0], w0.x, a); a = fmaf(A1[0], w1.x, a); a = fmaf(A2[0], w2.x, a);
            a = fmaf(A0[1], w0.y, a); a = fmaf(A1[1], w1.y, a); a = fmaf(A2[1], w2.y, a);
            a = fmaf(A0[2], w0.z, a); a = fmaf(A1[2], w1.z, a); a = fmaf(A2[2], w2.z, a);
            a = fmaf(A0[3], w0.w, a); a = fmaf(A1[3], w1.w, a); a = fmaf(A2[3], w2.w, a);
            acc[j] = a;
        }
    }
    float* out_g = out + g * 4096;
#pragma unroll
    for (int j = 0; j < 16; j++) out_g[(ob * 16 + j) * 64 + l] = acc[j];
}

// ---------------------------------------------------------------------------
// Elementwise BN3 + ReLU (channel = (idx>>6)&63)
__global__ void bn_relu_elt_kernel(const float* __restrict__ in,
                                   const float* __restrict__ st,
                                   const float* __restrict__ gamma,
                                   const float* __restrict__ beta,
                                   float* __restrict__ out) {
    int idx = blockIdx.x * 256 + threadIdx.x;
    int c = (idx >> 6) & 63;
    float mean = st[c] * (1.f / BN_COUNT);
    float var = st[64 + c] * (1.f / BN_COUNT) - mean * mean;
    float inv = rsqrtf(var + EPS);
    float sc = gamma[c] * inv;
    out[idx] = fmaxf(fmaf(in[idx], sc, beta[c] - mean * sc), 0.f);
}

// ---------------------------------------------------------------------------
// fp32 GEMM: C[M,N] = act(A[M,K] @ W[K,N] + bias). Tile 32x64, 128 threads,
// 4x4 micro-tiles. grid = (M/32, N/64).
__global__ void gemm_bias_act_kernel(const float* __restrict__ A,
                                     const float* __restrict__ W,
                                     const float* __restrict__ bias,
                                     float* __restrict__ C,
                                     int M, int N, int K, int relu) {
    __shared__ float As[16][36];   // [k][m], padded to float4 alignment
    __shared__ float Bs[16][64];   // [k][n]
    int bm = blockIdx.x * 32, bn = blockIdx.y * 64;
    int tid = threadIdx.x;
    int row4 = (tid >> 4) * 4;
    int col4 = (tid & 15) * 4;
    float acc[4][4] = {};

    for (int k0 = 0; k0 < K; k0 += 16) {
#pragma unroll
        for (int t = 0; t < 4; t++) {
            int idx = tid + t * 128;          // 0..511
            int r = idx >> 4, kk = idx & 15;
            As[kk][r] = A[(bm + r) * K + k0 + kk];
        }
#pragma unroll
        for (int t = 0; t < 8; t++) {
            int idx = tid + t * 128;          // 0..1023
            int r = idx >> 6, n = idx & 63;
            Bs[r][n] = W[(k0 + r) * N + bn + n];
        }
        __syncthreads();
#pragma unroll
        for (int kk = 0; kk < 16; kk++) {
            float4 a = *(const float4*)&As[kk][row4];
            float4 b = *(const float4*)&Bs[kk][col4];
            float av[4] = {a.x, a.y, a.z, a.w};
            float bv[4] = {b.x, b.y, b.z, b.w};
#pragma unroll
            for (int i = 0; i < 4; i++)
#pragma unroll
                for (int j = 0; j < 4; j++)
                    acc[i][j] = fmaf(av[i], bv[j], acc[i][j]);
        }
        __syncthreads();
    }
#pragma unroll
    for (int i = 0; i < 4; i++) {
#pragma unroll
        for (int j = 0; j < 4; j++) {
            float v = acc[i][j] + bias[bn + col4 + j];
            if (relu) v = fmaxf(v, 0.f);
            C[(bm + row4 + i) * N + bn + col4 + j] = v;
        }
    }
}

// ---------------------------------------------------------------------------
// Head: logits = act[1024,256] @ wp[256,16] + bp, then log_softmax(dim=1).
// 16 graphs per block, 16 threads per graph.
__global__ void head_kernel(const float* __restrict__ act,
                            const float* __restrict__ wp,
                            const float* __restrict__ bp,
                            float* __restrict__ out) {
    __shared__ float sl[256];
    int tid = threadIdx.x;
    int g = blockIdx.x * 16 + (tid >> 4);
    int a = tid & 15;
    const float* ar = act + g * 256;
    float acc = bp[a];
#pragma unroll 8
    for (int k = 0; k < 256; k++) acc = fmaf(ar[k], wp[k * 16 + a], acc);
    sl[tid] = acc;
    __syncthreads();
    int base = tid & ~15;
    float m = -1e30f;
#pragma unroll
    for (int j = 0; j < 16; j++) m = fmaxf(m, sl[base + j]);
    float s = 0.f;
#pragma unroll
    for (int j = 0; j < 16; j++) s += expf(sl[base + j] - m);
    out[g * 16 + a] = acc - m - logf(s);
}

// ---------------------------------------------------------------------------
extern "C" void kernel_launch(void* const* d_in, const int* in_sizes, int n_in,
                              void* d_out, int out_size) {
    const float* x   = (const float*)d_in[0];
    const int*   ei  = (const int*)d_in[1];
    const float* w1  = (const float*)d_in[2];
    const float* b1  = (const float*)d_in[3];
    const float* w2  = (const float*)d_in[4];
    const float* b2  = (const float*)d_in[5];
    const float* c2w = (const float*)d_in[6];
    const float* c2b = (const float*)d_in[7];
    const float* c3w = (const float*)d_in[8];
    const float* c3b = (const float*)d_in[9];
    const float* g1  = (const float*)d_in[10];
    const float* be1 = (const float*)d_in[11];
    const float* g2  = (const float*)d_in[12];
    const float* be2 = (const float*)d_in[13];
    const float* g3  = (const float*)d_in[14];
    const float* be3 = (const float*)d_in[15];
    const float* wm1 = (const float*)d_in[16];
    const float* bm1 = (const float*)d_in[17];
    const float* wm2 = (const float*)d_in[18];
    const float* bm2 = (const float*)d_in[19];
    const float* wm3 = (const float*)d_in[20];
    const float* bm3 = (const float*)d_in[21];
    const float* wp  = (const float*)d_in[22];
    const float* bp  = (const float*)d_in[23];
    float* out = (float*)d_out;

    float *buf1, *buf2, *act1, *act2, *st;
    cudaGetSymbolAddress((void**)&buf1, g_buf1);
    cudaGetSymbolAddress((void**)&buf2, g_buf2);
    cudaGetSymbolAddress((void**)&act1, g_act1);
    cudaGetSymbolAddress((void**)&act2, g_act2);
    cudaGetSymbolAddress((void**)&st, g_stats);

    cudaFuncSetAttribute(conv_bn_kernel<true>,
                         cudaFuncAttributeMaxDynamicSharedMemorySize, CONV_SMEM);
    cudaFuncSetAttribute(conv_bn_kernel<false>,
                         cudaFuncAttributeMaxDynamicSharedMemorySize, CONV_SMEM);

    zero_stats_kernel<<<1, 384>>>(st);
    edgeconv_kernel<<<NGRAPH, 256>>>(x, ei, w1, b1, w2, b2, buf1);
    stats_colch_kernel<<<NGRAPH, 256>>>(buf1, st);
    conv_bn_kernel<true><<<NGRAPH, 256, CONV_SMEM>>>(buf1, st, g1, be1, c2w, c2b, buf2);
    stats_rowch_kernel<<<NGRAPH, 256>>>(buf2, st + 128);
    conv_bn_kernel<false><<<NGRAPH, 256, CONV_SMEM>>>(buf2, st + 128, g2, be2, c3w, c3b, buf1);
    stats_rowch_kernel<<<NGRAPH, 256>>>(buf1, st + 256);
    bn_relu_elt_kernel<<<16384, 256>>>(buf1, st + 256, g3, be3, buf2);
    gemm_bias_act_kernel<<<dim3(32, 4), 128>>>(buf2, wm1, bm1, act1, 1024, 256, 4096, 1);
    gemm_bias_act_kernel<<<dim3(32, 4), 128>>>(act1, wm2, bm2, act2, 1024, 256, 256, 1);
    gemm_bias_act_kernel<<<dim3(32, 4), 128>>>(act2, wm3, bm3, act1, 1024, 256, 256, 1);
    head_kernel<<<64, 256>>>(act1, wp, bp, out);
}

// round 5
// speedup vs baseline: 1.3972x; 1.3972x over previous
#include <cuda_runtime.h>
#include <cuda_bf16.h>
#include <math.h>

// Problem constants
#define NGRAPH 1024
#define S 64
#define EPG 1024
#define E_TOTAL (NGRAPH * EPG)
#define HID 256
#define BN_COUNT 65536.0f
#define EPS 1e-5f

typedef unsigned long long ull;

union F4U { float4 f; ull u[2]; float s[4]; };
union F2U { float2 f; ull u; float s[2]; };

__device__ __forceinline__ ull splat2(float x) {
    ull r; asm("mov.b64 %0, {%1, %1};" : "=l"(r) : "f"(x)); return r;
}
__device__ __forceinline__ ull fma2(ull a, ull b, ull c) {
    ull d; asm("fma.rn.f32x2 %0, %1, %2, %3;" : "=l"(d) : "l"(a), "l"(b), "l"(c)); return d;
}

// Scratch (device globals; no allocation allowed)
__device__ float g_buf1[NGRAPH * S * S];      // 16 MB
__device__ float g_buf2[NGRAPH * S * S];      // 16 MB
__device__ float g_act1[NGRAPH * HID];
__device__ float g_act2[NGRAPH * HID];
__device__ float g_stats[384];                // 3 BNs x (64 sum + 64 sumsq)
__device__ float g_wt[2 * 12288];             // transposed conv weights

// ---------------------------------------------------------------------------
__global__ void zero_stats_kernel(float* st) {
    int i = threadIdx.x;
    if (i < 384) st[i] = 0.f;
}

// Transpose conv weights into [r=k*64+i][o] layout, both convs. 96 blocks x 256.
__global__ void prep_wt_kernel(const float* __restrict__ c2w,
                               const float* __restrict__ c3w,
                               float* __restrict__ wt) {
    int idx = blockIdx.x * 256 + threadIdx.x;     // 0..24575
    int j = idx;
    const float* cw = c2w;
    float* o = wt;
    if (j >= 12288) { j -= 12288; cw = c3w; o = wt + 12288; }
    int r = j >> 6, oo = j & 63;
    int k = r >> 6, i = r & 63;
    o[j] = cw[oo * 192 + i * 3 + k];
}

// ---------------------------------------------------------------------------
// EdgeConv: one block per graph, counting-sort edges by dst, serial accumulate.
// out layout: [(g*64 + node)*64 + feat]. Also accumulates BN1 stats (stg).
__global__ void edgeconv_kernel(const float* __restrict__ x,
                                const int* __restrict__ ei,
                                const float* __restrict__ w1,
                                const float* __restrict__ b1,
                                const float* __restrict__ w2,
                                const float* __restrict__ b2,
                                float* __restrict__ out,
                                float* __restrict__ stg) {
    __shared__ float sx[64];
    __shared__ float sw2[4][64];
    __shared__ float sb2v[64];
    __shared__ float sw1v[8];
    __shared__ float sb1v[4];
    __shared__ int s_src[EPG];
    __shared__ int s_d[EPG];
    __shared__ float shh[EPG * 4];
    __shared__ int cnt[64], off[64], pos[64];
    __shared__ float ps[4][64], pq[4][64];

    int g = blockIdx.x, tid = threadIdx.x;
    const int* srcp = ei + g * EPG;
    const int* dstp = ei + E_TOTAL + g * EPG;

    if (tid < 64) {
        sx[tid] = x[g * 64 + tid];
        sb2v[tid] = b2[tid];
        sw2[0][tid] = w2[tid];
        sw2[1][tid] = w2[64 + tid];
        sw2[2][tid] = w2[128 + tid];
        sw2[3][tid] = w2[192 + tid];
        cnt[tid] = 0;
    }
    if (tid < 8) sw1v[tid] = w1[tid];
    if (tid < 4) sb1v[tid] = b1[tid];
    __syncthreads();

    for (int e = tid; e < EPG; e += 256) {
        int s = srcp[e] & 63;
        int d = dstp[e] & 63;
        s_src[e] = s;
        s_d[e] = d;
        atomicAdd(&cnt[d], 1);
    }
    __syncthreads();
    if (tid == 0) {
        int a = 0;
        for (int i = 0; i < 64; i++) { off[i] = a; a += cnt[i]; }
    }
    __syncthreads();
    if (tid < 64) pos[tid] = off[tid];
    __syncthreads();

    float wa0 = sw1v[0], wa1 = sw1v[1], wa2 = sw1v[2], wa3 = sw1v[3];
    float wb0 = sw1v[4], wb1 = sw1v[5], wb2 = sw1v[6], wb3 = sw1v[7];
    float c0 = sb1v[0], c1 = sb1v[1], c2 = sb1v[2], c3 = sb1v[3];
    for (int e = tid; e < EPG; e += 256) {
        int d = s_d[e];
        float xi = sx[d];
        float xd = sx[s_src[e]] - xi;
        float h0 = fmaxf(fmaf(xd, wb0, fmaf(xi, wa0, c0)), 0.f);
        float h1 = fmaxf(fmaf(xd, wb1, fmaf(xi, wa1, c1)), 0.f);
        float h2 = fmaxf(fmaf(xd, wb2, fmaf(xi, wa2, c2)), 0.f);
        float h3 = fmaxf(fmaf(xd, wb3, fmaf(xi, wa3, c3)), 0.f);
        int p = atomicAdd(&pos[d], 1);
        *(float4*)&shh[p * 4] = make_float4(h0, h1, h2, h3);
    }
    __syncthreads();

    int f = tid & 63, dq = tid >> 6;
    float u0 = sw2[0][f], u1 = sw2[1][f], u2 = sw2[2][f], u3 = sw2[3][f];
    float bb = sb2v[f];
    float* out_g = out + g * 4096;
    float ssum = 0.f, sq = 0.f;
    for (int d = dq; d < 64; d += 4) {
        int st0 = off[d], en = st0 + cnt[d];
        float acc = bb * (float)(en - st0);
        for (int e = st0; e < en; e++) {
            float4 h = *(const float4*)&shh[e * 4];
            acc = fmaf(h.x, u0, acc);
            acc = fmaf(h.y, u1, acc);
            acc = fmaf(h.z, u2, acc);
            acc = fmaf(h.w, u3, acc);
        }
        out_g[d * 64 + f] = acc;
        ssum += acc;
        sq += acc * acc;
    }
    ps[dq][f] = ssum;
    pq[dq][f] = sq;
    __syncthreads();
    if (tid < 64) {
        atomicAdd(&stg[tid], ps[0][tid] + ps[1][tid] + ps[2][tid] + ps[3][tid]);
        atomicAdd(&stg[64 + tid], pq[0][tid] + pq[1][tid] + pq[2][tid] + pq[3][tid]);
    }
}

// ---------------------------------------------------------------------------
// Fused BN(+ReLU) + Conv1d(64,64,3,pad=1) as im2col GEMM with f32x2 FMA.
// TIN=true: input node-major in[(l)*64+i]; false: chan-major in[(i)*64+l].
// Output chan-major [(o)*64+l]; accumulates next BN stats into st_out.
#define CONV_SMEM ((192 * 68 + 192 * 64 + 128) * 4)
template <bool TIN>
__global__ void conv_gemm_kernel(const float* __restrict__ in,
                                 const float* __restrict__ st_in,
                                 const float* __restrict__ gamma,
                                 const float* __restrict__ beta,
                                 const float* __restrict__ wt,
                                 const float* __restrict__ cb,
                                 float* __restrict__ out,
                                 float* __restrict__ st_out) {
    extern __shared__ float smem[];
    float* Bm = smem;                    // [192][68] im2col
    float* Ws = smem + 192 * 68;         // [192][64] weights
    float* sscale = Ws + 192 * 64;       // [64]
    float* sshift = sscale + 64;         // [64]

    int g = blockIdx.x, tid = threadIdx.x;

    {
        const float4* w4 = (const float4*)wt;
        float4* d4 = (float4*)Ws;
#pragma unroll
        for (int t = 0; t < 12; t++) d4[tid + t * 256] = w4[tid + t * 256];
    }
    if (tid < 64) {
        float mean = st_in[tid] * (1.f / BN_COUNT);
        float var = st_in[64 + tid] * (1.f / BN_COUNT) - mean * mean;
        float inv = rsqrtf(var + EPS);
        float sc = gamma[tid] * inv;
        sscale[tid] = sc;
        sshift[tid] = beta[tid] - mean * sc;
    }
    __syncthreads();

    const float* in_g = in + g * 4096;
    for (int idx = tid; idx < 4096; idx += 256) {
        int i, l;
        if (TIN) { l = idx >> 6; i = idx & 63; }
        else     { i = idx >> 6; l = idx & 63; }
        float v = in_g[idx];
        Bm[(64 + i) * 68 + l] = fmaxf(fmaf(v, sscale[i], sshift[i]), 0.f);
    }
    __syncthreads();
    for (int idx = tid; idx < 8192; idx += 256) {
        int l = idx & 63, i = (idx >> 6) & 63;
        if (idx < 4096) Bm[i * 68 + l]         = (l == 0)  ? 0.f : Bm[(64 + i) * 68 + l - 1];
        else            Bm[(128 + i) * 68 + l] = (l == 63) ? 0.f : Bm[(64 + i) * 68 + l + 1];
    }
    __syncthreads();

    int o4 = (tid >> 4) * 4, l4 = (tid & 15) * 4;
    ull acc[4][2];
#pragma unroll
    for (int i = 0; i < 4; i++) {
        ull b = splat2(cb[o4 + i]);
        acc[i][0] = b; acc[i][1] = b;
    }
#pragma unroll 4
    for (int r = 0; r < 192; r++) {
        F4U bv; bv.f = *(const float4*)&Bm[r * 68 + l4];
        F4U wv; wv.f = *(const float4*)&Ws[r * 64 + o4];
#pragma unroll
        for (int i = 0; i < 4; i++) {
            ull a = splat2(wv.s[i]);
            acc[i][0] = fma2(a, bv.u[0], acc[i][0]);
            acc[i][1] = fma2(a, bv.u[1], acc[i][1]);
        }
    }
    float* out_g = out + g * 4096;
#pragma unroll
    for (int i = 0; i < 4; i++) {
        F4U c;
        c.u[0] = acc[i][0]; c.u[1] = acc[i][1];
        *(float4*)&out_g[(o4 + i) * 64 + l4] = c.f;
        float s = c.s[0] + c.s[1] + c.s[2] + c.s[3];
        float q = c.s[0]*c.s[0] + c.s[1]*c.s[1] + c.s[2]*c.s[2] + c.s[3]*c.s[3];
#pragma unroll
        for (int w = 1; w < 16; w <<= 1) {
            s += __shfl_xor_sync(0xffffffffu, s, w);
            q += __shfl_xor_sync(0xffffffffu, q, w);
        }
        if ((tid & 15) == 0) {
            atomicAdd(&st_out[o4 + i], s);
            atomicAdd(&st_out[64 + o4 + i], q);
        }
    }
}

// ---------------------------------------------------------------------------
// Vectorized BN3 + ReLU. elem e = idx*4; channel c = (idx>>4)&63.
__global__ void bn_relu_elt_kernel(const float4* __restrict__ in,
                                   const float* __restrict__ st,
                                   const float* __restrict__ gamma,
                                   const float* __restrict__ beta,
                                   float4* __restrict__ out) {
    int idx = blockIdx.x * 256 + threadIdx.x;
    int c = (idx >> 4) & 63;
    float mean = st[c] * (1.f / BN_COUNT);
    float var = st[64 + c] * (1.f / BN_COUNT) - mean * mean;
    float inv = rsqrtf(var + EPS);
    float sc = gamma[c] * inv;
    float sh = beta[c] - mean * sc;
    float4 v = in[idx];
    float4 r;
    r.x = fmaxf(fmaf(v.x, sc, sh), 0.f);
    r.y = fmaxf(fmaf(v.y, sc, sh), 0.f);
    r.z = fmaxf(fmaf(v.z, sc, sh), 0.f);
    r.w = fmaxf(fmaf(v.w, sc, sh), 0.f);
    out[idx] = r;
}

// ---------------------------------------------------------------------------
// fp32x2 GEMM: tile 32(M)x64(N), 128 threads, 4x4 micro. blockIdx.z = K-split.
// nz==1: final write with bias (+relu). nz>1: partial write to C + zi*M*N (no bias).
__global__ void gemm_f2_kernel(const float* __restrict__ A,
                               const float* __restrict__ W,
                               const float* __restrict__ bias,
                               float* __restrict__ C,
                               int M, int N, int K, int KS, int relu) {
    __shared__ float As[16][36];
    __shared__ float Bs[16][64];
    int bm = blockIdx.x * 32, bn = blockIdx.y * 64;
    int zi = blockIdx.z, nz = gridDim.z;
    int kbeg = zi * KS;
    int tid = threadIdx.x;
    int row4 = (tid >> 4) * 4;
    int col4 = (tid & 15) * 4;
    ull acc[4][2];
    if (nz == 1) {
        F4U b; b.f = *(const float4*)&bias[bn + col4];
#pragma unroll
        for (int i = 0; i < 4; i++) { acc[i][0] = b.u[0]; acc[i][1] = b.u[1]; }
    } else {
#pragma unroll
        for (int i = 0; i < 4; i++) { acc[i][0] = 0ull; acc[i][1] = 0ull; }
    }

    for (int k0 = kbeg; k0 < kbeg + KS; k0 += 16) {
#pragma unroll
        for (int t = 0; t < 4; t++) {
            int idx = tid + t * 128;
            int r = idx >> 4, kk = idx & 15;
            As[kk][r] = A[(bm + r) * K + k0 + kk];
        }
#pragma unroll
        for (int t = 0; t < 8; t++) {
            int idx = tid + t * 128;
            int r = idx >> 6, n = idx & 63;
            Bs[r][n] = W[(k0 + r) * N + bn + n];
        }
        __syncthreads();
#pragma unroll
        for (int kk = 0; kk < 16; kk++) {
            F4U bv; bv.f = *(const float4*)&Bs[kk][col4];
            float4 av = *(const float4*)&As[kk][row4];
            float as[4] = {av.x, av.y, av.z, av.w};
#pragma unroll
            for (int i = 0; i < 4; i++) {
                ull a = splat2(as[i]);
                acc[i][0] = fma2(a, bv.u[0], acc[i][0]);
                acc[i][1] = fma2(a, bv.u[1], acc[i][1]);
            }
        }
        __syncthreads();
    }
    float* Co = C + (nz > 1 ? (size_t)zi * M * N : 0);
#pragma unroll
    for (int i = 0; i < 4; i++) {
        F4U c;
        c.u[0] = acc[i][0]; c.u[1] = acc[i][1];
        if (relu && nz == 1) {
            c.s[0] = fmaxf(c.s[0], 0.f);
            c.s[1] = fmaxf(c.s[1], 0.f);
            c.s[2] = fmaxf(c.s[2], 0.f);
            c.s[3] = fmaxf(c.s[3], 0.f);
        }
        *(float4*)&Co[(bm + row4 + i) * N + bn + col4] = c.f;
    }
}

// Combine 4 K-split partials + bias + relu. i4 = float4 index. N=256.
__global__ void combine4_relu_kernel(const float* __restrict__ p,
                                     const float* __restrict__ bias,
                                     float* __restrict__ out) {
    int i4 = blockIdx.x * 256 + threadIdx.x;
    int e = i4 * 4;
    int n = e & 255;
    float4 a = *(const float4*)&p[e];
    float4 b = *(const float4*)&p[262144 + e];
    float4 c = *(const float4*)&p[524288 + e];
    float4 d = *(const float4*)&p[786432 + e];
    float4 bb = *(const float4*)&bias[n];
    float4 r;
    r.x = fmaxf(a.x + b.x + c.x + d.x + bb.x, 0.f);
    r.y = fmaxf(a.y + b.y + c.y + d.y + bb.y, 0.f);
    r.z = fmaxf(a.z + b.z + c.z + d.z + bb.z, 0.f);
    r.w = fmaxf(a.w + b.w + c.w + d.w + bb.w, 0.f);
    *(float4*)&out[e] = r;
}

// ---------------------------------------------------------------------------
// Head: logits = act[1024,256] @ wp[256,16] + bp, log_softmax.
__global__ void head_kernel(const float* __restrict__ act,
                            const float* __restrict__ wp,
                            const float* __restrict__ bp,
                            float* __restrict__ out) {
    __shared__ float sl[256];
    int tid = threadIdx.x;
    int g = blockIdx.x * 16 + (tid >> 4);
    int a = tid & 15;
    const float* ar = act + g * 256;
    float acc = bp[a];
#pragma unroll 8
    for (int k = 0; k < 256; k++) acc = fmaf(ar[k], wp[k * 16 + a], acc);
    sl[tid] = acc;
    __syncthreads();
    int base = tid & ~15;
    float m = -1e30f;
#pragma unroll
    for (int j = 0; j < 16; j++) m = fmaxf(m, sl[base + j]);
    float s = 0.f;
#pragma unroll
    for (int j = 0; j < 16; j++) s += expf(sl[base + j] - m);
    out[g * 16 + a] = acc - m - logf(s);
}

// ---------------------------------------------------------------------------
extern "C" void kernel_launch(void* const* d_in, const int* in_sizes, int n_in,
                              void* d_out, int out_size) {
    const float* x   = (const float*)d_in[0];
    const int*   ei  = (const int*)d_in[1];
    const float* w1  = (const float*)d_in[2];
    const float* b1  = (const float*)d_in[3];
    const float* w2  = (const float*)d_in[4];
    const float* b2  = (const float*)d_in[5];
    const float* c2w = (const float*)d_in[6];
    const float* c2b = (const float*)d_in[7];
    const float* c3w = (const float*)d_in[8];
    const float* c3b = (const float*)d_in[9];
    const float* g1  = (const float*)d_in[10];
    const float* be1 = (const float*)d_in[11];
    const float* g2  = (const float*)d_in[12];
    const float* be2 = (const float*)d_in[13];
    const float* g3  = (const float*)d_in[14];
    const float* be3 = (const float*)d_in[15];
    const float* wm1 = (const float*)d_in[16];
    const float* bm1 = (const float*)d_in[17];
    const float* wm2 = (const float*)d_in[18];
    const float* bm2 = (const float*)d_in[19];
    const float* wm3 = (const float*)d_in[20];
    const float* bm3 = (const float*)d_in[21];
    const float* wp  = (const float*)d_in[22];
    const float* bp  = (const float*)d_in[23];
    float* out = (float*)d_out;

    float *buf1, *buf2, *act1, *act2, *st, *wt;
    cudaGetSymbolAddress((void**)&buf1, g_buf1);
    cudaGetSymbolAddress((void**)&buf2, g_buf2);
    cudaGetSymbolAddress((void**)&act1, g_act1);
    cudaGetSymbolAddress((void**)&act2, g_act2);
    cudaGetSymbolAddress((void**)&st, g_stats);
    cudaGetSymbolAddress((void**)&wt, g_wt);

    cudaFuncSetAttribute(conv_gemm_kernel<true>,
                         cudaFuncAttributeMaxDynamicSharedMemorySize, CONV_SMEM);
    cudaFuncSetAttribute(conv_gemm_kernel<false>,
                         cudaFuncAttributeMaxDynamicSharedMemorySize, CONV_SMEM);

    zero_stats_kernel<<<1, 384>>>(st);
    prep_wt_kernel<<<96, 256>>>(c2w, c3w, wt);
    edgeconv_kernel<<<NGRAPH, 256>>>(x, ei, w1, b1, w2, b2, buf1, st);
    conv_gemm_kernel<true><<<NGRAPH, 256, CONV_SMEM>>>(buf1, st, g1, be1, wt, c2b, buf2, st + 128);
    conv_gemm_kernel<false><<<NGRAPH, 256, CONV_SMEM>>>(buf2, st + 128, g2, be2, wt + 12288, c3b, buf1, st + 256);
    bn_relu_elt_kernel<<<4096, 256>>>((const float4*)buf1, st + 256, g3, be3, (float4*)buf2);
    // GEMM1 with K-split 4 (partials into buf1, then combine)
    gemm_f2_kernel<<<dim3(32, 4, 4), 128>>>(buf2, wm1, bm1, buf1, 1024, 256, 4096, 1024, 0);
    combine4_relu_kernel<<<256, 256>>>(buf1, bm1, act1);
    gemm_f2_kernel<<<dim3(32, 4, 1), 128>>>(act1, wm2, bm2, act2, 1024, 256, 256, 256, 1);
    gemm_f2_kernel<<<dim3(32, 4, 1), 128>>>(act2, wm3, bm3, act1, 1024, 256, 256, 256, 1);
    head_kernel<<<64, 256>>>(act1, wp, bp, out);
}

// round 7
// speedup vs baseline: 1.7980x; 1.2868x over previous
#include <cuda_runtime.h>
#include <cuda_bf16.h>
#include <math.h>
#include <stdint.h>

// Problem constants
#define NGRAPH 1024
#define S 64
#define EPG 1024
#define E_TOTAL (NGRAPH * EPG)
#define HID 256
#define BN_COUNT 65536.0f
#define EPS 1e-5f

typedef unsigned long long ull;

union F4U { float4 f; ull u[2]; float s[4]; };

__device__ __forceinline__ ull splat2(float x) {
    ull r; asm("mov.b64 %0, {%1, %1};" : "=l"(r) : "f"(x)); return r;
}
__device__ __forceinline__ ull fma2(ull a, ull b, ull c) {
    ull d; asm("fma.rn.f32x2 %0, %1, %2, %3;" : "=l"(d) : "l"(a), "l"(b), "l"(c)); return d;
}
__device__ __forceinline__ float2 un2(ull v) {
    float2 f; asm("mov.b64 {%0, %1}, %2;" : "=f"(f.x), "=f"(f.y) : "l"(v)); return f;
}

// Scratch (device globals; no allocation allowed)
__device__ float g_buf1[NGRAPH * S * S];      // 16 MB
__device__ float g_buf2[NGRAPH * S * S];      // 16 MB (also holds GEMM1 partials? no - buf1)
__device__ float g_act1[NGRAPH * HID];
__device__ float g_act2[NGRAPH * HID];
__device__ float g_stats[384];                // 3 BNs x (64 sum + 64 sumsq)
__device__ float g_wt[2 * 12288];             // transposed conv weights [r][o]

// ---------------------------------------------------------------------------
__global__ void zero_stats_kernel(float* st) {
    int i = threadIdx.x;
    if (i < 384) st[i] = 0.f;
}

// Transpose conv weights into [r=k*64+i][o] layout, both convs. 96 blocks x 256.
__global__ void prep_wt_kernel(const float* __restrict__ c2w,
                               const float* __restrict__ c3w,
                               float* __restrict__ wt) {
    int idx = blockIdx.x * 256 + threadIdx.x;     // 0..24575
    int j = idx;
    const float* cw = c2w;
    float* o = wt;
    if (j >= 12288) { j -= 12288; cw = c3w; o = wt + 12288; }
    int r = j >> 6, oo = j & 63;
    int k = r >> 6, i = r & 63;
    o[j] = cw[oo * 192 + i * 3 + k];
}

// ---------------------------------------------------------------------------
// EdgeConv: one block per graph, counting-sort edges by dst, serial accumulate.
// out layout: [(g*64 + node)*64 + feat]. Also accumulates BN1 stats (stg).
__global__ void edgeconv_kernel(const float* __restrict__ x,
                                const int* __restrict__ ei,
                                const float* __restrict__ w1,
                                const float* __restrict__ b1,
                                const float* __restrict__ w2,
                                const float* __restrict__ b2,
                                float* __restrict__ out,
                                float* __restrict__ stg) {
    __shared__ float sx[64];
    __shared__ float sw2[4][64];
    __shared__ float sb2v[64];
    __shared__ float sw1v[8];
    __shared__ float sb1v[4];
    __shared__ int s_src[EPG];
    __shared__ int s_d[EPG];
    __shared__ float shh[EPG * 4];
    __shared__ int cnt[64], off[64], pos[64];
    __shared__ float ps[4][64], pq[4][64];

    int g = blockIdx.x, tid = threadIdx.x;
    const int* srcp = ei + g * EPG;
    const int* dstp = ei + E_TOTAL + g * EPG;

    if (tid < 64) {
        sx[tid] = x[g * 64 + tid];
        sb2v[tid] = b2[tid];
        sw2[0][tid] = w2[tid];
        sw2[1][tid] = w2[64 + tid];
        sw2[2][tid] = w2[128 + tid];
        sw2[3][tid] = w2[192 + tid];
        cnt[tid] = 0;
    }
    if (tid < 8) sw1v[tid] = w1[tid];
    if (tid < 4) sb1v[tid] = b1[tid];
    __syncthreads();

    for (int e = tid; e < EPG; e += 256) {
        int s = srcp[e] & 63;
        int d = dstp[e] & 63;
        s_src[e] = s;
        s_d[e] = d;
        atomicAdd(&cnt[d], 1);
    }
    __syncthreads();
    if (tid == 0) {
        int a = 0;
        for (int i = 0; i < 64; i++) { off[i] = a; a += cnt[i]; }
    }
    __syncthreads();
    if (tid < 64) pos[tid] = off[tid];
    __syncthreads();

    float wa0 = sw1v[0], wa1 = sw1v[1], wa2 = sw1v[2], wa3 = sw1v[3];
    float wb0 = sw1v[4], wb1 = sw1v[5], wb2 = sw1v[6], wb3 = sw1v[7];
    float c0 = sb1v[0], c1 = sb1v[1], c2 = sb1v[2], c3 = sb1v[3];
    for (int e = tid; e < EPG; e += 256) {
        int d = s_d[e];
        float xi = sx[d];
        float xd = sx[s_src[e]] - xi;
        float h0 = fmaxf(fmaf(xd, wb0, fmaf(xi, wa0, c0)), 0.f);
        float h1 = fmaxf(fmaf(xd, wb1, fmaf(xi, wa1, c1)), 0.f);
        float h2 = fmaxf(fmaf(xd, wb2, fmaf(xi, wa2, c2)), 0.f);
        float h3 = fmaxf(fmaf(xd, wb3, fmaf(xi, wa3, c3)), 0.f);
        int p = atomicAdd(&pos[d], 1);
        *(float4*)&shh[p * 4] = make_float4(h0, h1, h2, h3);
    }
    __syncthreads();

    int f = tid & 63, dq = tid >> 6;
    float u0 = sw2[0][f], u1 = sw2[1][f], u2 = sw2[2][f], u3 = sw2[3][f];
    float bb = sb2v[f];
    float* out_g = out + g * 4096;
    float ssum = 0.f, sq = 0.f;
    for (int d = dq; d < 64; d += 4) {
        int st0 = off[d], en = st0 + cnt[d];
        float acc = bb * (float)(en - st0);
        for (int e = st0; e < en; e++) {
            float4 h = *(const float4*)&shh[e * 4];
            acc = fmaf(h.x, u0, acc);
            acc = fmaf(h.y, u1, acc);
            acc = fmaf(h.z, u2, acc);
            acc = fmaf(h.w, u3, acc);
        }
        out_g[d * 64 + f] = acc;
        ssum += acc;
        sq += acc * acc;
    }
    ps[dq][f] = ssum;
    pq[dq][f] = sq;
    __syncthreads();
    if (tid < 64) {
        atomicAdd(&stg[tid], ps[0][tid] + ps[1][tid] + ps[2][tid] + ps[3][tid]);
        atomicAdd(&stg[64 + tid], pq[0][tid] + pq[1][tid] + pq[2][tid] + pq[3][tid]);
    }
}

// ---------------------------------------------------------------------------
// Fused BN(+ReLU) + Conv1d(64,64,3,pad=1), 8x8 register-blocked f32x2 GEMM.
// 2 graphs per CTA, 128 threads, thread = 8 out-ch x 8 l-slots (l strided 16).
// TIN=true: input node-major in[l*64+i]; false: chan-major in[i*64+l].
// Output chan-major [(o)*64+l]; accumulates next BN stats into st_out.
#define CONV_SMEM ((2 * 64 * 66 + 192 * 64 + 128) * 4)
template <bool TIN>
__global__ __launch_bounds__(128, 2)
void conv8_kernel(const float* __restrict__ in,
                  const float* __restrict__ st_in,
                  const float* __restrict__ gamma,
                  const float* __restrict__ beta,
                  const float* __restrict__ wt,
                  const float* __restrict__ cb,
                  float* __restrict__ out,
                  float* __restrict__ st_out) {
    extern __shared__ float smem[];
    float* Sg = smem;                 // [2][64][66], halo at 0 and 65
    float* Ws = smem + 2 * 4224;      // [192][64]
    float* Ssc = Ws + 12288;          // [64]
    float* Ssh = Ssc + 64;            // [64]

    int tid = threadIdx.x;
    int g0 = blockIdx.x * 2;

    // weights -> smem ([r][o] layout, float4)
    {
        const float4* w4 = (const float4*)wt;
        float4* d4 = (float4*)Ws;
#pragma unroll
        for (int t = 0; t < 24; t++) d4[tid + t * 128] = w4[tid + t * 128];
    }
    if (tid < 64) {
        float mean = st_in[tid] * (1.f / BN_COUNT);
        float var = st_in[64 + tid] * (1.f / BN_COUNT) - mean * mean;
        float inv = rsqrtf(var + EPS);
        float sc = gamma[tid] * inv;
        Ssc[tid] = sc;
        Ssh[tid] = beta[tid] - mean * sc;
    }
    {   // zero halos
        int g = tid >> 6, i = tid & 63;
        Sg[g * 4224 + i * 66] = 0.f;
        Sg[g * 4224 + i * 66 + 65] = 0.f;
    }
    __syncthreads();

    // Stage BN+ReLU input into Sg[g][i][l+1]
    const float4* in4 = (const float4*)(in + (size_t)g0 * 4096);
#pragma unroll
    for (int t = 0; t < 16; t++) {
        int idx4 = tid + t * 128;               // 0..2047
        int g = idx4 >> 10;
        int e = (idx4 & 1023) * 4;
        float4 v = in4[idx4];
        if (TIN) {
            int l = e >> 6, i0 = e & 63;
            float* b = &Sg[g * 4224 + l + 1];
            b[(i0 + 0) * 66] = fmaxf(fmaf(v.x, Ssc[i0],     Ssh[i0]),     0.f);
            b[(i0 + 1) * 66] = fmaxf(fmaf(v.y, Ssc[i0 + 1], Ssh[i0 + 1]), 0.f);
            b[(i0 + 2) * 66] = fmaxf(fmaf(v.z, Ssc[i0 + 2], Ssh[i0 + 2]), 0.f);
            b[(i0 + 3) * 66] = fmaxf(fmaf(v.w, Ssc[i0 + 3], Ssh[i0 + 3]), 0.f);
        } else {
            int i = e >> 6, l0 = e & 63;
            float sc = Ssc[i], sh = Ssh[i];
            float* b = &Sg[g * 4224 + i * 66 + l0 + 1];
            b[0] = fmaxf(fmaf(v.x, sc, sh), 0.f);
            b[1] = fmaxf(fmaf(v.y, sc, sh), 0.f);
            b[2] = fmaxf(fmaf(v.z, sc, sh), 0.f);
            b[3] = fmaxf(fmaf(v.w, sc, sh), 0.f);
        }
    }
    __syncthreads();

    int ot = tid >> 4, lt = tid & 15;
    int o8 = ot * 8;
    ull acc[4][8];
    {
        F4U b0; b0.f = *(const float4*)&cb[o8];
        F4U b1; b1.f = *(const float4*)&cb[o8 + 4];
#pragma unroll
        for (int j = 0; j < 8; j++) {
            acc[0][j] = b0.u[0]; acc[1][j] = b0.u[1];
            acc[2][j] = b1.u[0]; acc[3][j] = b1.u[1];
        }
    }
    // l-slot j: g = j>>2, l = (j&3)*16 + lt
#pragma unroll 2
    for (int r = 0; r < 192; r++) {
        int k = r >> 6, i = r & 63;
        const float* Wr = &Ws[r * 64 + o8];
        F4U w0; w0.f = *(const float4*)Wr;
        F4U w1; w1.f = *(const float4*)(Wr + 4);
        const float* Bb = &Sg[i * 66 + k + lt];
#pragma unroll
        for (int j = 0; j < 8; j++) {
            float bv = Bb[(j >> 2) * 4224 + (j & 3) * 16];
            ull bs = splat2(bv);
            acc[0][j] = fma2(w0.u[0], bs, acc[0][j]);
            acc[1][j] = fma2(w0.u[1], bs, acc[1][j]);
            acc[2][j] = fma2(w1.u[0], bs, acc[2][j]);
            acc[3][j] = fma2(w1.u[1], bs, acc[3][j]);
        }
    }

    // Epilogue: store chan-major + BN stats (reduce over 16 lt lanes)
#pragma unroll
    for (int qd = 0; qd < 4; qd++) {
        float s0 = 0.f, q0 = 0.f, s1 = 0.f, q1 = 0.f;
#pragma unroll
        for (int j = 0; j < 8; j++) {
            float2 v = un2(acc[qd][j]);
            int g = g0 + (j >> 2);
            int l = (j & 3) * 16 + lt;
            float* og = out + (size_t)g * 4096;
            og[(o8 + 2 * qd) * 64 + l]     = v.x;
            og[(o8 + 2 * qd + 1) * 64 + l] = v.y;
            s0 += v.x; q0 += v.x * v.x;
            s1 += v.y; q1 += v.y * v.y;
        }
#pragma unroll
        for (int w = 1; w < 16; w <<= 1) {
            s0 += __shfl_xor_sync(0xffffffffu, s0, w);
            q0 += __shfl_xor_sync(0xffffffffu, q0, w);
            s1 += __shfl_xor_sync(0xffffffffu, s1, w);
            q1 += __shfl_xor_sync(0xffffffffu, q1, w);
        }
        if (lt == 0) {
            atomicAdd(&st_out[o8 + 2 * qd], s0);
            atomicAdd(&st_out[64 + o8 + 2 * qd], q0);
            atomicAdd(&st_out[o8 + 2 * qd + 1], s1);
            atomicAdd(&st_out[64 + o8 + 2 * qd + 1], q1);
        }
    }
}

// ---------------------------------------------------------------------------
// Vectorized BN3 + ReLU (chan-major input).
__global__ void bn_relu_elt_kernel(const float4* __restrict__ in,
                                   const float* __restrict__ st,
                                   const float* __restrict__ gamma,
                                   const float* __restrict__ beta,
                                   float4* __restrict__ out) {
    int idx = blockIdx.x * 256 + threadIdx.x;
    int c = (idx >> 4) & 63;
    float mean = st[c] * (1.f / BN_COUNT);
    float var = st[64 + c] * (1.f / BN_COUNT) - mean * mean;
    float inv = rsqrtf(var + EPS);
    float sc = gamma[c] * inv;
    float sh = beta[c] - mean * sc;
    float4 v = in[idx];
    float4 r;
    r.x = fmaxf(fmaf(v.x, sc, sh), 0.f);
    r.y = fmaxf(fmaf(v.y, sc, sh), 0.f);
    r.z = fmaxf(fmaf(v.z, sc, sh), 0.f);
    r.w = fmaxf(fmaf(v.w, sc, sh), 0.f);
    out[idx] = r;
}

// ---------------------------------------------------------------------------
// 8x8 register-blocked f32x2 GEMM for GEMM1: tile 64M x 128N, 128 threads.
// blockIdx.z = K-split slab; partials written to C + zi*M*N (no bias).
__global__ __launch_bounds__(128)
void gemm8_kernel(const float* __restrict__ A,
                  const float* __restrict__ W,
                  float* __restrict__ C,
                  int M, int N, int K, int KS) {
    __shared__ float As[16][68];    // [kk][m]
    __shared__ float Bs[16][128];   // [kk][n]
    int bm = blockIdx.x * 64, bn = blockIdx.y * 128;
    int zi = blockIdx.z;
    int kbeg = zi * KS;
    int tid = threadIdx.x;
    int mt = tid >> 4, nt = tid & 15;
    int m8 = mt * 8, n8 = nt * 8;
    ull acc[8][4];
#pragma unroll
    for (int i = 0; i < 8; i++)
#pragma unroll
        for (int j = 0; j < 4; j++) acc[i][j] = 0ull;

    for (int k0 = kbeg; k0 < kbeg + KS; k0 += 16) {
#pragma unroll
        for (int t = 0; t < 2; t++) {
            int fi = tid + t * 128;            // 0..255 float4 in 64x16 A tile
            int r = fi >> 2, c4 = (fi & 3) * 4;
            float4 v = *(const float4*)&A[(size_t)(bm + r) * K + k0 + c4];
            As[c4 + 0][r] = v.x;
            As[c4 + 1][r] = v.y;
            As[c4 + 2][r] = v.z;
            As[c4 + 3][r] = v.w;
        }
#pragma unroll
        for (int t = 0; t < 4; t++) {
            int fi = tid + t * 128;            // 0..511 float4 in 16x128 B tile
            int r = fi >> 5, c = (fi & 31) * 4;
            *(float4*)&Bs[r][c] = *(const float4*)&W[(size_t)(k0 + r) * N + bn + c];
        }
        __syncthreads();
#pragma unroll
        for (int kk = 0; kk < 16; kk++) {
            F4U a0; a0.f = *(const float4*)&As[kk][m8];
            F4U a1; a1.f = *(const float4*)&As[kk][m8 + 4];
            F4U b0; b0.f = *(const float4*)&Bs[kk][n8];
            F4U b1; b1.f = *(const float4*)&Bs[kk][n8 + 4];
            float am[8] = {a0.s[0], a0.s[1], a0.s[2], a0.s[3],
                           a1.s[0], a1.s[1], a1.s[2], a1.s[3]};
#pragma unroll
            for (int i = 0; i < 8; i++) {
                ull as_ = splat2(am[i]);
                acc[i][0] = fma2(as_, b0.u[0], acc[i][0]);
                acc[i][1] = fma2(as_, b0.u[1], acc[i][1]);
                acc[i][2] = fma2(as_, b1.u[0], acc[i][2]);
                acc[i][3] = fma2(as_, b1.u[1], acc[i][3]);
            }
        }
        __syncthreads();
    }
    float* Co = C + (size_t)zi * M * N;
#pragma unroll
    for (int i = 0; i < 8; i++) {
        F4U c0, c1;
        c0.u[0] = acc[i][0]; c0.u[1] = acc[i][1];
        c1.u[0] = acc[i][2]; c1.u[1] = acc[i][3];
        float* row = &Co[(size_t)(bm + m8 + i) * N + bn + n8];
        *(float4*)row = c0.f;
        *(float4*)(row + 4) = c1.f;
    }
}

// Combine 8 K-split partials + bias + relu. i4 = float4 index (65536 total).
__global__ void combine8_relu_kernel(const float* __restrict__ p,
                                     const float* __restrict__ bias,
                                     float* __restrict__ out) {
    int i4 = blockIdx.x * 256 + threadIdx.x;
    int e = i4 * 4;
    int n = e & 255;
    float4 acc = *(const float4*)&bias[n];
#pragma unroll
    for (int z = 0; z < 8; z++) {
        float4 v = *(const float4*)&p[(size_t)z * 262144 + e];
        acc.x += v.x; acc.y += v.y; acc.z += v.z; acc.w += v.w;
    }
    acc.x = fmaxf(acc.x, 0.f);
    acc.y = fmaxf(acc.y, 0.f);
    acc.z = fmaxf(acc.z, 0.f);
    acc.w = fmaxf(acc.w, 0.f);
    *(float4*)&out[e] = acc;
}

// ---------------------------------------------------------------------------
// fp32x2 GEMM for the small 256x256 layers (tile 32x64, 4x4 micro).
__global__ void gemm_f2_kernel(const float* __restrict__ A,
                               const float* __restrict__ W,
                               const float* __restrict__ bias,
                               float* __restrict__ C,
                               int M, int N, int K, int relu) {
    __shared__ float As[16][36];
    __shared__ float Bs[16][64];
    int bm = blockIdx.x * 32, bn = blockIdx.y * 64;
    int tid = threadIdx.x;
    int row4 = (tid >> 4) * 4;
    int col4 = (tid & 15) * 4;
    ull acc[4][2];
    {
        F4U b; b.f = *(const float4*)&bias[bn + col4];
#pragma unroll
        for (int i = 0; i < 4; i++) { acc[i][0] = b.u[0]; acc[i][1] = b.u[1]; }
    }
    for (int k0 = 0; k0 < K; k0 += 16) {
#pragma unroll
        for (int t = 0; t < 4; t++) {
            int idx = tid + t * 128;
            int r = idx >> 4, kk = idx & 15;
            As[kk][r] = A[(bm + r) * K + k0 + kk];
        }
#pragma unroll
        for (int t = 0; t < 8; t++) {
            int idx = tid + t * 128;
            int r = idx >> 6, n = idx & 63;
            Bs[r][n] = W[(k0 + r) * N + bn + n];
        }
        __syncthreads();
#pragma unroll
        for (int kk = 0; kk < 16; kk++) {
            F4U bv; bv.f = *(const float4*)&Bs[kk][col4];
            float4 av = *(const float4*)&As[kk][row4];
            float as_[4] = {av.x, av.y, av.z, av.w};
#pragma unroll
            for (int i = 0; i < 4; i++) {
                ull a = splat2(as_[i]);
                acc[i][0] = fma2(a, bv.u[0], acc[i][0]);
                acc[i][1] = fma2(a, bv.u[1], acc[i][1]);
            }
        }
        __syncthreads();
    }
#pragma unroll
    for (int i = 0; i < 4; i++) {
        F4U c;
        c.u[0] = acc[i][0]; c.u[1] = acc[i][1];
        if (relu) {
            c.s[0] = fmaxf(c.s[0], 0.f);
            c.s[1] = fmaxf(c.s[1], 0.f);
            c.s[2] = fmaxf(c.s[2], 0.f);
            c.s[3] = fmaxf(c.s[3], 0.f);
        }
        *(float4*)&C[(bm + row4 + i) * N + bn + col4] = c.f;
    }
}

// ---------------------------------------------------------------------------
__global__ void head_kernel(const float* __restrict__ act,
                            const float* __restrict__ wp,
                            const float* __restrict__ bp,
                            float* __restrict__ out) {
    __shared__ float sl[256];
    int tid = threadIdx.x;
    int g = blockIdx.x * 16 + (tid >> 4);
    int a = tid & 15;
    const float* ar = act + g * 256;
    float acc = bp[a];
#pragma unroll 8
    for (int k = 0; k < 256; k++) acc = fmaf(ar[k], wp[k * 16 + a], acc);
    sl[tid] = acc;
    __syncthreads();
    int base = tid & ~15;
    float m = -1e30f;
#pragma unroll
    for (int j = 0; j < 16; j++) m = fmaxf(m, sl[base + j]);
    float s = 0.f;
#pragma unroll
    for (int j = 0; j < 16; j++) s += expf(sl[base + j] - m);
    out[g * 16 + a] = acc - m - logf(s);
}

// ---------------------------------------------------------------------------
extern "C" void kernel_launch(void* const* d_in, const int* in_sizes, int n_in,
                              void* d_out, int out_size) {
    const float* x   = (const float*)d_in[0];
    const int*   ei  = (const int*)d_in[1];
    const float* w1  = (const float*)d_in[2];
    const float* b1  = (const float*)d_in[3];
    const float* w2  = (const float*)d_in[4];
    const float* b2  = (const float*)d_in[5];
    const float* c2w = (const float*)d_in[6];
    const float* c2b = (const float*)d_in[7];
    const float* c3w = (const float*)d_in[8];
    const float* c3b = (const float*)d_in[9];
    const float* g1  = (const float*)d_in[10];
    const float* be1 = (const float*)d_in[11];
    const float* g2  = (const float*)d_in[12];
    const float* be2 = (const float*)d_in[13];
    const float* g3  = (const float*)d_in[14];
    const float* be3 = (const float*)d_in[15];
    const float* wm1 = (const float*)d_in[16];
    const float* bm1 = (const float*)d_in[17];
    const float* wm2 = (const float*)d_in[18];
    const float* bm2 = (const float*)d_in[19];
    const float* wm3 = (const float*)d_in[20];
    const float* bm3 = (const float*)d_in[21];
    const float* wp  = (const float*)d_in[22];
    const float* bp  = (const float*)d_in[23];
    float* out = (float*)d_out;

    float *buf1, *buf2, *act1, *act2, *st, *wt;
    cudaGetSymbolAddress((void**)&buf1, g_buf1);
    cudaGetSymbolAddress((void**)&buf2, g_buf2);
    cudaGetSymbolAddress((void**)&act1, g_act1);
    cudaGetSymbolAddress((void**)&act2, g_act2);
    cudaGetSymbolAddress((void**)&st, g_stats);
    cudaGetSymbolAddress((void**)&wt, g_wt);

    cudaFuncSetAttribute(conv8_kernel<true>,
                         cudaFuncAttributeMaxDynamicSharedMemorySize, CONV_SMEM);
    cudaFuncSetAttribute(conv8_kernel<false>,
                         cudaFuncAttributeMaxDynamicSharedMemorySize, CONV_SMEM);

    zero_stats_kernel<<<1, 384>>>(st);
    prep_wt_kernel<<<96, 256>>>(c2w, c3w, wt);
    edgeconv_kernel<<<NGRAPH, 256>>>(x, ei, w1, b1, w2, b2, buf1, st);
    conv8_kernel<true><<<512, 128, CONV_SMEM>>>(buf1, st, g1, be1, wt, c2b, buf2, st + 128);
    conv8_kernel<false><<<512, 128, CONV_SMEM>>>(buf2, st + 128, g2, be2, wt + 12288, c3b, buf1, st + 256);
    bn_relu_elt_kernel<<<4096, 256>>>((const float4*)buf1, st + 256, g3, be3, (float4*)buf2);
    // GEMM1: K-split 8 partials into buf1, then combine
    gemm8_kernel<<<dim3(16, 2, 8), 128>>>(buf2, wm1, buf1, 1024, 256, 4096, 512);
    combine8_relu_kernel<<<256, 256>>>(buf1, bm1, act1);
    gemm_f2_kernel<<<dim3(32, 4), 128>>>(act1, wm2, bm2, act2, 1024, 256, 256, 1);
    gemm_f2_kernel<<<dim3(32, 4), 128>>>(act2, wm3, bm3, act1, 1024, 256, 256, 1);
    head_kernel<<<64, 256>>>(act1, wp, bp, out);
}

// round 10
// speedup vs baseline: 2.0087x; 1.1172x over previous
#include <cuda_runtime.h>
#include <cuda_bf16.h>
#include <math.h>
#include <stdint.h>

// Problem constants
#define NGRAPH 1024
#define EPG 1024
#define E_TOTAL (NGRAPH * EPG)
#define HID 256
#define BN_COUNT 65536.0f
#define EPS 1e-5f

typedef unsigned long long ull;

union F4U { float4 f; ull u[2]; float s[4]; };
union F2U { float2 f; ull u; float s[2]; };

__device__ __forceinline__ ull splat2(float x) {
    ull r; asm("mov.b64 %0, {%1, %1};" : "=l"(r) : "f"(x)); return r;
}
__device__ __forceinline__ ull fma2(ull a, ull b, ull c) {
    ull d; asm("fma.rn.f32x2 %0, %1, %2, %3;" : "=l"(d) : "l"(a), "l"(b), "l"(c)); return d;
}
__device__ __forceinline__ float2 un2(ull v) {
    float2 f; asm("mov.b64 {%0, %1}, %2;" : "=f"(f.x), "=f"(f.y) : "l"(v)); return f;
}

// Scratch (device globals; no allocation allowed)
__device__ float g_buf1[NGRAPH * 64 * 64];    // 16 MB
__device__ float g_buf2[NGRAPH * 64 * 64];    // 16 MB (also GEMM1 partials)
__device__ float g_act1[NGRAPH * HID];
__device__ float g_act2[NGRAPH * HID];
__device__ float g_stats[384];                // 3 BNs x (64 sum + 64 sumsq)
__device__ float g_wt[2 * 12288];             // transposed conv weights [r][o]

// ---------------------------------------------------------------------------
__global__ void zero_stats_kernel(float* st) {
    int i = threadIdx.x;
    if (i < 384) st[i] = 0.f;
}

// Transpose conv weights into [r=k*64+i][o] layout, both convs. 96 blocks x 256.
__global__ void prep_wt_kernel(const float* __restrict__ c2w,
                               const float* __restrict__ c3w,
                               float* __restrict__ wt) {
    int idx = blockIdx.x * 256 + threadIdx.x;     // 0..24575
    int j = idx;
    const float* cw = c2w;
    float* o = wt;
    if (j >= 12288) { j -= 12288; cw = c3w; o = wt + 12288; }
    int r = j >> 6, oo = j & 63;
    int k = r >> 6, i = r & 63;
    o[j] = cw[oo * 192 + i * 3 + k];
}

// ---------------------------------------------------------------------------
// EdgeConv: one block per graph, counting-sort edges by dst, f32x2 accumulate.
// out layout: [(g*64 + node)*64 + feat]. Also accumulates BN1 stats (stg).
__global__ void edgeconv_kernel(const float* __restrict__ x,
                                const int* __restrict__ ei,
                                const float* __restrict__ w1,
                                const float* __restrict__ b1,
                                const float* __restrict__ w2,
                                const float* __restrict__ b2,
                                float* __restrict__ out,
                                float* __restrict__ stg) {
    __shared__ float sx[64];
    __shared__ float sw2[4][64];
    __shared__ float sb2v[64];
    __shared__ float sw1v[8];
    __shared__ float sb1v[4];
    __shared__ int s_src[EPG];
    __shared__ int s_d[EPG];
    __shared__ float shh[EPG * 4];
    __shared__ int cnt[64], off[64], pos[64];
    __shared__ float2 ps2[8][32], pq2[8][32];

    int g = blockIdx.x, tid = threadIdx.x;
    const int* srcp = ei + g * EPG;
    const int* dstp = ei + E_TOTAL + g * EPG;

    if (tid < 64) {
        sx[tid] = x[g * 64 + tid];
        sb2v[tid] = b2[tid];
        sw2[0][tid] = w2[tid];
        sw2[1][tid] = w2[64 + tid];
        sw2[2][tid] = w2[128 + tid];
        sw2[3][tid] = w2[192 + tid];
        cnt[tid] = 0;
    }
    if (tid < 8) sw1v[tid] = w1[tid];
    if (tid < 4) sb1v[tid] = b1[tid];
    __syncthreads();

    for (int e = tid; e < EPG; e += 256) {
        int s = srcp[e] & 63;
        int d = dstp[e] & 63;
        s_src[e] = s;
        s_d[e] = d;
        atomicAdd(&cnt[d], 1);
    }
    __syncthreads();
    if (tid == 0) {
        int a = 0;
        for (int i = 0; i < 64; i++) { off[i] = a; a += cnt[i]; }
    }
    __syncthreads();
    if (tid < 64) pos[tid] = off[tid];
    __syncthreads();

    float wa0 = sw1v[0], wa1 = sw1v[1], wa2 = sw1v[2], wa3 = sw1v[3];
    float wb0 = sw1v[4], wb1 = sw1v[5], wb2 = sw1v[6], wb3 = sw1v[7];
    float c0 = sb1v[0], c1 = sb1v[1], c2 = sb1v[2], c3 = sb1v[3];
    for (int e = tid; e < EPG; e += 256) {
        int d = s_d[e];
        float xi = sx[d];
        float xd = sx[s_src[e]] - xi;
        float h0 = fmaxf(fmaf(xd, wb0, fmaf(xi, wa0, c0)), 0.f);
        float h1 = fmaxf(fmaf(xd, wb1, fmaf(xi, wa1, c1)), 0.f);
        float h2 = fmaxf(fmaf(xd, wb2, fmaf(xi, wa2, c2)), 0.f);
        float h3 = fmaxf(fmaf(xd, wb3, fmaf(xi, wa3, c3)), 0.f);
        int p = atomicAdd(&pos[d], 1);
        *(float4*)&shh[p * 4] = make_float4(h0, h1, h2, h3);
    }
    __syncthreads();

    // f32x2 accumulate: thread = feature pair f2, d strided by 8 (warp-uniform d)
    int f2 = tid & 31, dq = tid >> 5;
    F2U u0p, u1p, u2p, u3p, bbp;
    u0p.f = *(const float2*)&sw2[0][f2 * 2];
    u1p.f = *(const float2*)&sw2[1][f2 * 2];
    u2p.f = *(const float2*)&sw2[2][f2 * 2];
    u3p.f = *(const float2*)&sw2[3][f2 * 2];
    bbp.f = *(const float2*)&sb2v[f2 * 2];
    float* out_g = out + g * 4096;
    float2 Sacc = make_float2(0.f, 0.f), Qacc = make_float2(0.f, 0.f);
    for (int d = dq; d < 64; d += 8) {
        int st0 = off[d], en = st0 + cnt[d];
        float n = (float)(en - st0);
        F2U a0, a1;
        a0.f.x = bbp.f.x * n; a0.f.y = bbp.f.y * n;
        a1.f.x = 0.f; a1.f.y = 0.f;
        ull acc0 = a0.u, acc1 = a1.u;
        for (int e = st0; e < en; e++) {
            float4 h = *(const float4*)&shh[e * 4];
            acc0 = fma2(splat2(h.x), u0p.u, acc0);
            acc1 = fma2(splat2(h.y), u1p.u, acc1);
            acc0 = fma2(splat2(h.z), u2p.u, acc0);
            acc1 = fma2(splat2(h.w), u3p.u, acc1);
        }
        float2 v0 = un2(acc0), v1 = un2(acc1);
        float2 c;
        c.x = v0.x + v1.x;
        c.y = v0.y + v1.y;
        *(float2*)&out_g[d * 64 + f2 * 2] = c;
        Sacc.x += c.x; Sacc.y += c.y;
        Qacc.x += c.x * c.x; Qacc.y += c.y * c.y;
    }
    ps2[dq][f2] = Sacc;
    pq2[dq][f2] = Qacc;
    __syncthreads();
    if (tid < 32) {
        float sx_ = 0.f, sy_ = 0.f;
#pragma unroll
        for (int w = 0; w < 8; w++) { sx_ += ps2[w][tid].x; sy_ += ps2[w][tid].y; }
        atomicAdd(&stg[2 * tid], sx_);
        atomicAdd(&stg[2 * tid + 1], sy_);
    } else if (tid < 64) {
        int f = tid - 32;
        float qx = 0.f, qy = 0.f;
#pragma unroll
        for (int w = 0; w < 8; w++) { qx += pq2[w][f].x; qy += pq2[w][f].y; }
        atomicAdd(&stg[64 + 2 * f], qx);
        atomicAdd(&stg[64 + 2 * f + 1], qy);
    }
}

// ---------------------------------------------------------------------------
// Fused BN(+ReLU) + Conv1d(64,64,3,pad=1), 8x8-class register blocking, f32x2.
// 256 threads, 2 graphs per CTA. Thread = 8 out-ch (as 4 o-pairs) x 4 l-slots
// (l = (lt&15) + jj*16, graph = lt>>4). Graph stride 4240 floats (bank offset 16).
// Weights broadcast per warp (same ot for all lanes). Conflict-free B loads.
#define GSTRIDE 4240
#define CONV_SMEM ((2 * GSTRIDE + 12288 + 128) * 4)
template <bool TIN>
__global__ __launch_bounds__(256, 2)
void conv8_kernel(const float* __restrict__ in,
                  const float* __restrict__ st_in,
                  const float* __restrict__ gamma,
                  const float* __restrict__ beta,
                  const float* __restrict__ wt,
                  const float* __restrict__ cb,
                  float* __restrict__ out,
                  float* __restrict__ st_out) {
    extern __shared__ float smem[];
    float* Sg = smem;                 // [2][GSTRIDE]: per graph [64 ch][66], halo 0/65
    float* Ws = smem + 2 * GSTRIDE;   // [192][64]
    float* Ssc = Ws + 12288;          // [64]
    float* Ssh = Ssc + 64;            // [64]

    int tid = threadIdx.x;
    int g0 = blockIdx.x * 2;

    // weights -> smem ([r][o] layout, float4): 3072 float4
    {
        const float4* w4 = (const float4*)wt;
        float4* d4 = (float4*)Ws;
#pragma unroll
        for (int t = 0; t < 12; t++) d4[tid + t * 256] = w4[tid + t * 256];
    }
    if (tid < 64) {
        float mean = st_in[tid] * (1.f / BN_COUNT);
        float var = st_in[64 + tid] * (1.f / BN_COUNT) - mean * mean;
        float inv = rsqrtf(var + EPS);
        float sc = gamma[tid] * inv;
        Ssc[tid] = sc;
        Ssh[tid] = beta[tid] - mean * sc;
    }
    if (tid < 128) {   // zero halos
        int g = tid >> 6, i = tid & 63;
        Sg[g * GSTRIDE + i * 66] = 0.f;
        Sg[g * GSTRIDE + i * 66 + 65] = 0.f;
    }
    __syncthreads();

    // Stage BN+ReLU input into Sg[g][i*66 + l + 1]
    const float4* in4 = (const float4*)(in + (size_t)g0 * 4096);
#pragma unroll
    for (int t = 0; t < 8; t++) {
        int idx4 = tid + t * 256;               // 0..2047
        int g = idx4 >> 10;
        int e = (idx4 & 1023) * 4;
        float4 v = in4[idx4];
        if (TIN) {
            int l = e >> 6, i0 = e & 63;
            float* b = &Sg[g * GSTRIDE + l + 1];
            b[(i0 + 0) * 66] = fmaxf(fmaf(v.x, Ssc[i0],     Ssh[i0]),     0.f);
            b[(i0 + 1) * 66] = fmaxf(fmaf(v.y, Ssc[i0 + 1], Ssh[i0 + 1]), 0.f);
            b[(i0 + 2) * 66] = fmaxf(fmaf(v.z, Ssc[i0 + 2], Ssh[i0 + 2]), 0.f);
            b[(i0 + 3) * 66] = fmaxf(fmaf(v.w, Ssc[i0 + 3], Ssh[i0 + 3]), 0.f);
        } else {
            int i = e >> 6, l0 = e & 63;
            float sc = Ssc[i], sh = Ssh[i];
            float* b = &Sg[g * GSTRIDE + i * 66 + l0 + 1];
            b[0] = fmaxf(fmaf(v.x, sc, sh), 0.f);
            b[1] = fmaxf(fmaf(v.y, sc, sh), 0.f);
            b[2] = fmaxf(fmaf(v.z, sc, sh), 0.f);
            b[3] = fmaxf(fmaf(v.w, sc, sh), 0.f);
        }
    }
    __syncthreads();

    int ot = tid >> 5, lt = tid & 31;
    int o8 = ot * 8;
    int gg = lt >> 4, llo = lt & 15;
    ull acc[4][4];                     // [o-pair][l-slot]
    {
        F4U b0; b0.f = *(const float4*)&cb[o8];
        F4U b1; b1.f = *(const float4*)&cb[o8 + 4];
#pragma unroll
        for (int jj = 0; jj < 4; jj++) {
            acc[0][jj] = b0.u[0]; acc[1][jj] = b0.u[1];
            acc[2][jj] = b1.u[0]; acc[3][jj] = b1.u[1];
        }
    }

    const float* Wp = &Ws[o8];
    const float* Bg = &Sg[gg * GSTRIDE + llo];
#pragma unroll 1
    for (int k = 0; k < 3; k++) {
        const float* Bp = Bg + k;
#pragma unroll 4
        for (int i = 0; i < 64; i++) {
            F4U w0; w0.f = *(const float4*)Wp;
            F4U w1; w1.f = *(const float4*)(Wp + 4);
            float b0 = Bp[0], b1 = Bp[16], b2 = Bp[32], b3 = Bp[48];
            ull s0 = splat2(b0), s1 = splat2(b1), s2 = splat2(b2), s3 = splat2(b3);
            acc[0][0] = fma2(w0.u[0], s0, acc[0][0]);
            acc[1][0] = fma2(w0.u[1], s0, acc[1][0]);
            acc[2][0] = fma2(w1.u[0], s0, acc[2][0]);
            acc[3][0] = fma2(w1.u[1], s0, acc[3][0]);
            acc[0][1] = fma2(w0.u[0], s1, acc[0][1]);
            acc[1][1] = fma2(w0.u[1], s1, acc[1][1]);
            acc[2][1] = fma2(w1.u[0], s1, acc[2][1]);
            acc[3][1] = fma2(w1.u[1], s1, acc[3][1]);
            acc[0][2] = fma2(w0.u[0], s2, acc[0][2]);
            acc[1][2] = fma2(w0.u[1], s2, acc[1][2]);
            acc[2][2] = fma2(w1.u[0], s2, acc[2][2]);
            acc[3][2] = fma2(w1.u[1], s2, acc[3][2]);
            acc[0][3] = fma2(w0.u[0], s3, acc[0][3]);
            acc[1][3] = fma2(w0.u[1], s3, acc[1][3]);
            acc[2][3] = fma2(w1.u[0], s3, acc[2][3]);
            acc[3][3] = fma2(w1.u[1], s3, acc[3][3]);
            Wp += 64;
            Bp += 66;
        }
    }

    // Epilogue: store chan-major + BN stats (warp = both graphs, all l)
    float* og = out + (size_t)(g0 + gg) * 4096;
#pragma unroll
    for (int q = 0; q < 4; q++) {
        int o = o8 + 2 * q;
        float s0 = 0.f, q0 = 0.f, s1 = 0.f, q1 = 0.f;
#pragma unroll
        for (int jj = 0; jj < 4; jj++) {
            float2 v = un2(acc[q][jj]);
            int l = llo + jj * 16;
            og[o * 64 + l] = v.x;
            og[(o + 1) * 64 + l] = v.y;
            s0 += v.x; q0 += v.x * v.x;
            s1 += v.y; q1 += v.y * v.y;
        }
#pragma unroll
        for (int w = 1; w < 32; w <<= 1) {
            s0 += __shfl_xor_sync(0xffffffffu, s0, w);
            q0 += __shfl_xor_sync(0xffffffffu, q0, w);
            s1 += __shfl_xor_sync(0xffffffffu, s1, w);
            q1 += __shfl_xor_sync(0xffffffffu, q1, w);
        }
        if (lt == 0) {
            atomicAdd(&st_out[o], s0);
            atomicAdd(&st_out[64 + o], q0);
            atomicAdd(&st_out[o + 1], s1);
            atomicAdd(&st_out[64 + o + 1], q1);
        }
    }
}

// ---------------------------------------------------------------------------
// 8x8 register-blocked f32x2 GEMM for GEMM1 with fused BN3+ReLU on A.
// Tile 64M x 128N, 128 threads, blockIdx.z = K-split slab; partials to C+zi*M*N.
__global__ __launch_bounds__(128)
void gemm8_kernel(const float* __restrict__ A,
                  const float* __restrict__ W,
                  const float* __restrict__ st,
                  const float* __restrict__ gamma,
                  const float* __restrict__ beta,
                  float* __restrict__ C,
                  int M, int N, int K, int KS) {
    __shared__ float As[16][68];    // [kk][m]
    __shared__ float Bs[16][128];   // [kk][n]
    __shared__ float Fsc[64], Fsh[64];
    int bm = blockIdx.x * 64, bn = blockIdx.y * 128;
    int zi = blockIdx.z;
    int kbeg = zi * KS;
    int tid = threadIdx.x;
    if (tid < 64) {
        float mean = st[tid] * (1.f / BN_COUNT);
        float var = st[64 + tid] * (1.f / BN_COUNT) - mean * mean;
        float inv = rsqrtf(var + EPS);
        float sc = gamma[tid] * inv;
        Fsc[tid] = sc;
        Fsh[tid] = beta[tid] - mean * sc;
    }
    __syncthreads();
    int mt = tid >> 4, nt = tid & 15;
    int m8 = mt * 8, n8 = nt * 8;
    ull acc[8][4];
#pragma unroll
    for (int i = 0; i < 8; i++)
#pragma unroll
        for (int j = 0; j < 4; j++) acc[i][j] = 0ull;

    for (int k0 = kbeg; k0 < kbeg + KS; k0 += 16) {
#pragma unroll
        for (int t = 0; t < 2; t++) {
            int fi = tid + t * 128;            // 0..255 float4 in 64x16 A tile
            int r = fi >> 2, c4 = (fi & 3) * 4;
            float4 v = *(const float4*)&A[(size_t)(bm + r) * K + k0 + c4];
            int ch = (k0 + c4) >> 6;
            float sc = Fsc[ch], sh = Fsh[ch];
            As[c4 + 0][r] = fmaxf(fmaf(v.x, sc, sh), 0.f);
            As[c4 + 1][r] = fmaxf(fmaf(v.y, sc, sh), 0.f);
            As[c4 + 2][r] = fmaxf(fmaf(v.z, sc, sh), 0.f);
            As[c4 + 3][r] = fmaxf(fmaf(v.w, sc, sh), 0.f);
        }
#pragma unroll
        for (int t = 0; t < 4; t++) {
            int fi = tid + t * 128;            // 0..511 float4 in 16x128 B tile
            int r = fi >> 5, c = (fi & 31) * 4;
            *(float4*)&Bs[r][c] = *(const float4*)&W[(size_t)(k0 + r) * N + bn + c];
        }
        __syncthreads();
#pragma unroll
        for (int kk = 0; kk < 16; kk++) {
            F4U a0; a0.f = *(const float4*)&As[kk][m8];
            F4U a1; a1.f = *(const float4*)&As[kk][m8 + 4];
            F4U b0; b0.f = *(const float4*)&Bs[kk][n8];
            F4U b1; b1.f = *(const float4*)&Bs[kk][n8 + 4];
            float am[8] = {a0.s[0], a0.s[1], a0.s[2], a0.s[3],
                           a1.s[0], a1.s[1], a1.s[2], a1.s[3]};
#pragma unroll
            for (int i = 0; i < 8; i++) {
                ull as_ = splat2(am[i]);
                acc[i][0] = fma2(as_, b0.u[0], acc[i][0]);
                acc[i][1] = fma2(as_, b0.u[1], acc[i][1]);
                acc[i][2] = fma2(as_, b1.u[0], acc[i][2]);
                acc[i][3] = fma2(as_, b1.u[1], acc[i][3]);
            }
        }
        __syncthreads();
    }
    float* Co = C + (size_t)zi * M * N;
#pragma unroll
    for (int i = 0; i < 8; i++) {
        F4U c0, c1;
        c0.u[0] = acc[i][0]; c0.u[1] = acc[i][1];
        c1.u[0] = acc[i][2]; c1.u[1] = acc[i][3];
        float* row = &Co[(size_t)(bm + m8 + i) * N + bn + n8];
        *(float4*)row = c0.f;
        *(float4*)(row + 4) = c1.f;
    }
}

// Combine 16 K-split partials + bias + relu. 256 blocks x 256 threads x float4.
__global__ void combine16_relu_kernel(const float* __restrict__ p,
                                      const float* __restrict__ bias,
                                      float* __restrict__ out) {
    int i4 = blockIdx.x * 256 + threadIdx.x;
    int e = i4 * 4;
    int n = e & 255;
    float4 acc = *(const float4*)&bias[n];
#pragma unroll
    for (int z = 0; z < 16; z++) {
        float4 v = *(const float4*)&p[(size_t)z * 262144 + e];
        acc.x += v.x; acc.y += v.y; acc.z += v.z; acc.w += v.w;
    }
    acc.x = fmaxf(acc.x, 0.f);
    acc.y = fmaxf(acc.y, 0.f);
    acc.z = fmaxf(acc.z, 0.f);
    acc.w = fmaxf(acc.w, 0.f);
    *(float4*)&out[e] = acc;
}

// ---------------------------------------------------------------------------
// fp32x2 GEMM for the small 256x256 layers (tile 32x64, 4x4 micro).
__global__ void gemm_f2_kernel(const float* __restrict__ A,
                               const float* __restrict__ W,
                               const float* __restrict__ bias,
                               float* __restrict__ C,
                               int M, int N, int K, int relu) {
    __shared__ float As[16][36];
    __shared__ float Bs[16][64];
    int bm = blockIdx.x * 32, bn = blockIdx.y * 64;
    int tid = threadIdx.x;
    int row4 = (tid >> 4) * 4;
    int col4 = (tid & 15) * 4;
    ull acc[4][2];
    {
        F4U b; b.f = *(const float4*)&bias[bn + col4];
#pragma unroll
        for (int i = 0; i < 4; i++) { acc[i][0] = b.u[0]; acc[i][1] = b.u[1]; }
    }
    for (int k0 = 0; k0 < K; k0 += 16) {
#pragma unroll
        for (int t = 0; t < 4; t++) {
            int idx = tid + t * 128;
            int r = idx >> 4, kk = idx & 15;
            As[kk][r] = A[(bm + r) * K + k0 + kk];
        }
#pragma unroll
        for (int t = 0; t < 8; t++) {
            int idx = tid + t * 128;
            int r = idx >> 6, n = idx & 63;
            Bs[r][n] = W[(k0 + r) * N + bn + n];
        }
        __syncthreads();
#pragma unroll
        for (int kk = 0; kk < 16; kk++) {
            F4U bv; bv.f = *(const float4*)&Bs[kk][col4];
            float4 av = *(const float4*)&As[kk][row4];
            float as_[4] = {av.x, av.y, av.z, av.w};
#pragma unroll
            for (int i = 0; i < 4; i++) {
                ull a = splat2(as_[i]);
                acc[i][0] = fma2(a, bv.u[0], acc[i][0]);
                acc[i][1] = fma2(a, bv.u[1], acc[i][1]);
            }
        }
        __syncthreads();
    }
#pragma unroll
    for (int i = 0; i < 4; i++) {
        F4U c;
        c.u[0] = acc[i][0]; c.u[1] = acc[i][1];
        if (relu) {
            c.s[0] = fmaxf(c.s[0], 0.f);
            c.s[1] = fmaxf(c.s[1], 0.f);
            c.s[2] = fmaxf(c.s[2], 0.f);
            c.s[3] = fmaxf(c.s[3], 0.f);
        }
        *(float4*)&C[(bm + row4 + i) * N + bn + col4] = c.f;
    }
}

// ---------------------------------------------------------------------------
__global__ void head_kernel(const float* __restrict__ act,
                            const float* __restrict__ wp,
                            const float* __restrict__ bp,
                            float* __restrict__ out) {
    __shared__ float sl[256];
    int tid = threadIdx.x;
    int g = blockIdx.x * 16 + (tid >> 4);
    int a = tid & 15;
    const float* ar = act + g * 256;
    float acc = bp[a];
#pragma unroll 8
    for (int k = 0; k < 256; k++) acc = fmaf(ar[k], wp[k * 16 + a], acc);
    sl[tid] = acc;
    __syncthreads();
    int base = tid & ~15;
    float m = -1e30f;
#pragma unroll
    for (int j = 0; j < 16; j++) m = fmaxf(m, sl[base + j]);
    float s = 0.f;
#pragma unroll
    for (int j = 0; j < 16; j++) s += expf(sl[base + j] - m);
    out[g * 16 + a] = acc - m - logf(s);
}

// ---------------------------------------------------------------------------
extern "C" void kernel_launch(void* const* d_in, const int* in_sizes, int n_in,
                              void* d_out, int out_size) {
    const float* x   = (const float*)d_in[0];
    const int*   ei  = (const int*)d_in[1];
    const float* w1  = (const float*)d_in[2];
    const float* b1  = (const float*)d_in[3];
    const float* w2  = (const float*)d_in[4];
    const float* b2  = (const float*)d_in[5];
    const float* c2w = (const float*)d_in[6];
    const float* c2b = (const float*)d_in[7];
    const float* c3w = (const float*)d_in[8];
    const float* c3b = (const float*)d_in[9];
    const float* g1  = (const float*)d_in[10];
    const float* be1 = (const float*)d_in[11];
    const float* g2  = (const float*)d_in[12];
    const float* be2 = (const float*)d_in[13];
    const float* g3  = (const float*)d_in[14];
    const float* be3 = (const float*)d_in[15];
    const float* wm1 = (const float*)d_in[16];
    const float* bm1 = (const float*)d_in[17];
    const float* wm2 = (const float*)d_in[18];
    const float* bm2 = (const float*)d_in[19];
    const float* wm3 = (const float*)d_in[20];
    const float* bm3 = (const float*)d_in[21];
    const float* wp  = (const float*)d_in[22];
    const float* bp  = (const float*)d_in[23];
    float* out = (float*)d_out;

    float *buf1, *buf2, *act1, *act2, *st, *wt;
    cudaGetSymbolAddress((void**)&buf1, g_buf1);
    cudaGetSymbolAddress((void**)&buf2, g_buf2);
    cudaGetSymbolAddress((void**)&act1, g_act1);
    cudaGetSymbolAddress((void**)&act2, g_act2);
    cudaGetSymbolAddress((void**)&st, g_stats);
    cudaGetSymbolAddress((void**)&wt, g_wt);

    cudaFuncSetAttribute(conv8_kernel<true>,
                         cudaFuncAttributeMaxDynamicSharedMemorySize, CONV_SMEM);
    cudaFuncSetAttribute(conv8_kernel<false>,
                         cudaFuncAttributeMaxDynamicSharedMemorySize, CONV_SMEM);

    zero_stats_kernel<<<1, 384>>>(st);
    prep_wt_kernel<<<96, 256>>>(c2w, c3w, wt);
    edgeconv_kernel<<<NGRAPH, 256>>>(x, ei, w1, b1, w2, b2, buf1, st);
    conv8_kernel<true><<<512, 256, CONV_SMEM>>>(buf1, st, g1, be1, wt, c2b, buf2, st + 128);
    conv8_kernel<false><<<512, 256, CONV_SMEM>>>(buf2, st + 128, g2, be2, wt + 12288, c3b, buf1, st + 256);
    // GEMM1 with fused BN3+ReLU on A; K-split 16 partials into buf2, combine
    gemm8_kernel<<<dim3(16, 2, 16), 128>>>(buf1, wm1, st + 256, g3, be3, buf2, 1024, 256, 4096, 256);
    combine16_relu_kernel<<<256, 256>>>(buf2, bm1, act1);
    gemm_f2_kernel<<<dim3(32, 4), 128>>>(act1, wm2, bm2, act2, 1024, 256, 256, 1);
    gemm_f2_kernel<<<dim3(32, 4), 128>>>(act2, wm3, bm3, act1, 1024, 256, 256, 1);
    head_kernel<<<64, 256>>>(act1, wp, bp, out);
}